// round 1
// baseline (speedup 1.0000x reference)
#include <cuda_runtime.h>
#include <cuda_bf16.h>
#include <math.h>

// Problem constants (from reference)
#define BB   32
#define DD   1024
#define TT   1000
#define VV   80
#define LMAX 200
#define BLANK 79
#define NEGV (-1e30f)

// Scratch (static device globals — no allocation allowed)
__device__ float g_h[(size_t)BB * TT * DD];     // 131 MB: relu(x W1 + b1), [B*T, D]
__device__ float g_lp[(size_t)BB * TT * VV];    // 10 MB: logits -> log_probs in place
__device__ float g_loss[BB];

// ---------------------------------------------------------------------------
// GEMM1: h[b,t,e] = relu( sum_d dec[b,d,t] * W1[d,e] + b1[e] )
// dec is [B, D, T] (T contiguous) -> A(k=d, m=t) is contiguous in m. W1 is [D,D]
// contiguous in n. Tile 128x128, K-tile 16, 256 threads, 8x8 per thread.
// ---------------------------------------------------------------------------
__global__ __launch_bounds__(256) void gemm1_kernel(
    const float* __restrict__ dec, const float* __restrict__ W1,
    const float* __restrict__ b1)
{
    __shared__ float As[16][128];
    __shared__ float Bs[16][128];

    const int b  = blockIdx.z;
    const int m0 = blockIdx.x * 128;   // t tile
    const int n0 = blockIdx.y * 128;   // e tile
    const int tid = threadIdx.x;
    const int tx = tid & 15;           // -> 8 columns
    const int ty = tid >> 4;           // -> 8 rows

    const float* A = dec + (size_t)b * DD * TT;

    float acc[8][8];
#pragma unroll
    for (int i = 0; i < 8; i++)
#pragma unroll
        for (int j = 0; j < 8; j++) acc[i][j] = 0.f;

    for (int k0 = 0; k0 < DD; k0 += 16) {
#pragma unroll
        for (int i = 0; i < 8; i++) {
            int idx = tid + i * 256;
            int kk = idx >> 7;
            int mm = idx & 127;
            int m  = m0 + mm;
            As[kk][mm] = (m < TT) ? A[(size_t)(k0 + kk) * TT + m] : 0.f;
            Bs[kk][mm] = W1[(size_t)(k0 + kk) * DD + n0 + mm];
        }
        __syncthreads();

#pragma unroll
        for (int kk = 0; kk < 16; kk++) {
            float a[8], w[8];
#pragma unroll
            for (int i = 0; i < 8; i++) a[i] = As[kk][ty * 8 + i];
#pragma unroll
            for (int j = 0; j < 8; j++) w[j] = Bs[kk][tx * 8 + j];
#pragma unroll
            for (int i = 0; i < 8; i++)
#pragma unroll
                for (int j = 0; j < 8; j++) acc[i][j] = fmaf(a[i], w[j], acc[i][j]);
        }
        __syncthreads();
    }

#pragma unroll
    for (int i = 0; i < 8; i++) {
        int m = m0 + ty * 8 + i;
        if (m >= TT) continue;
        float* hrow = g_h + ((size_t)b * TT + m) * DD;
#pragma unroll
        for (int j = 0; j < 8; j++) {
            int n = n0 + tx * 8 + j;
            hrow[n] = fmaxf(acc[i][j] + b1[n], 0.f);
        }
    }
}

// ---------------------------------------------------------------------------
// GEMM2: logits[row, v] = h[row, :] . W2[:, v] + b2[v], row in [0, B*T)
// Tile: 64 rows x 80 cols, blockDim (80, 4). Each thread: 16 rows, 1 column.
// ---------------------------------------------------------------------------
__global__ __launch_bounds__(320) void gemm2_kernel(
    const float* __restrict__ W2, const float* __restrict__ b2)
{
    __shared__ float Hs[16][64];
    __shared__ float Ws[16][VV];

    const int row0 = blockIdx.x * 64;
    const int v  = threadIdx.x;                 // 0..79
    const int ty = threadIdx.y;                 // 0..3
    const int tid = ty * 80 + v;

    float acc[16];
#pragma unroll
    for (int r = 0; r < 16; r++) acc[r] = 0.f;

    for (int k0 = 0; k0 < DD; k0 += 16) {
        for (int idx = tid; idx < 64 * 16; idx += 320) {
            int kk = idx & 15;
            int r  = idx >> 4;
            Hs[kk][r] = g_h[(size_t)(row0 + r) * DD + k0 + kk];
        }
        for (int idx = tid; idx < 16 * VV; idx += 320) {
            int vv = idx % VV;
            int kk = idx / VV;
            Ws[kk][vv] = W2[(size_t)(k0 + kk) * VV + vv];
        }
        __syncthreads();

#pragma unroll
        for (int kk = 0; kk < 16; kk++) {
            float w = Ws[kk][v];
#pragma unroll
            for (int r = 0; r < 16; r++)
                acc[r] = fmaf(Hs[kk][ty + 4 * r], w, acc[r]);
        }
        __syncthreads();
    }

    float bias = b2[v];
#pragma unroll
    for (int r = 0; r < 16; r++) {
        int row = row0 + ty + 4 * r;
        g_lp[(size_t)row * VV + v] = acc[r] + bias;
    }
}

// ---------------------------------------------------------------------------
// In-place log_softmax over V=80 per row; one warp per row.
// ---------------------------------------------------------------------------
__global__ __launch_bounds__(256) void logsoftmax_kernel()
{
    const int row  = blockIdx.x * 8 + (threadIdx.x >> 5);
    const int lane = threadIdx.x & 31;
    if (row >= BB * TT) return;
    float* p = g_lp + (size_t)row * VV;

    float mx = -INFINITY;
    for (int j = lane; j < VV; j += 32) mx = fmaxf(mx, p[j]);
#pragma unroll
    for (int o = 16; o > 0; o >>= 1) mx = fmaxf(mx, __shfl_xor_sync(0xffffffffu, mx, o));

    float s = 0.f;
    for (int j = lane; j < VV; j += 32) s += expf(p[j] - mx);
#pragma unroll
    for (int o = 16; o > 0; o >>= 1) s += __shfl_xor_sync(0xffffffffu, s, o);

    float lse = mx + logf(s);
    for (int j = lane; j < VV; j += 32) p[j] -= lse;
}

// ---------------------------------------------------------------------------
// CTC forward DP. One block per batch element; thread s = state s.
// ---------------------------------------------------------------------------
__global__ __launch_bounds__(448) void ctc_kernel(
    const int* __restrict__ tgt, const int* __restrict__ dlen,
    const int* __restrict__ tlen)
{
    const int b   = blockIdx.x;
    const int L   = tlen[b];
    const int S   = 2 * L + 1;
    const int len = dlen[b];
    const int s   = threadIdx.x;

    __shared__ float A[2][2 * LMAX + 1];
    __shared__ int   ext[2 * LMAX + 1];
    __shared__ unsigned char skip[2 * LMAX + 1];

    const float* lpb = g_lp + (size_t)b * TT * VV;

    if (s < S)
        ext[s] = (s & 1) ? tgt[b * LMAX + (s >> 1)] : BLANK;
    __syncthreads();

    if (s < S) {
        skip[s] = ((s & 1) && s >= 3 && ext[s] != ext[s - 2]) ? 1 : 0;
        float a0 = NEGV;
        if (s == 0)      a0 = lpb[BLANK];
        else if (s == 1) a0 = lpb[ext[1]];
        A[0][s] = a0;
    }
    __syncthreads();

    for (int t = 1; t < len; t++) {
        const int cur = t & 1, prev = cur ^ 1;
        if (s < S) {
            float a  = A[prev][s];
            float bv = (s >= 1) ? A[prev][s - 1] : NEGV;
            float cv = skip[s] ? A[prev][s - 2] : NEGV;
            float m  = fmaxf(a, fmaxf(bv, cv));
            float v  = m + logf(expf(a - m) + expf(bv - m) + expf(cv - m));
            A[cur][s] = v + lpb[t * VV + ext[s]];
        }
        __syncthreads();
    }

    if (s == 0) {
        const int f = (len - 1) & 1;
        float l1 = A[f][2 * L - 1];
        float l2 = A[f][2 * L];
        float m  = fmaxf(l1, l2);
        float last = m + logf(expf(l1 - m) + expf(l2 - m));
        float nll  = (last > 0.5f * NEGV) ? -last : 0.f;
        g_loss[b]  = nll / (float)len;
    }
}

// ---------------------------------------------------------------------------
// Final reduction: mean over batch -> scalar output.
// ---------------------------------------------------------------------------
__global__ __launch_bounds__(32) void reduce_kernel(float* __restrict__ out)
{
    float v = g_loss[threadIdx.x];
#pragma unroll
    for (int o = 16; o > 0; o >>= 1) v += __shfl_xor_sync(0xffffffffu, v, o);
    if (threadIdx.x == 0) out[0] = v * (1.0f / BB);
}

// ---------------------------------------------------------------------------
extern "C" void kernel_launch(void* const* d_in, const int* in_sizes, int n_in,
                              void* d_out, int out_size)
{
    const float* dec  = (const float*)d_in[0];
    const int*   tgt  = (const int*)  d_in[1];
    const int*   dlen = (const int*)  d_in[2];
    const int*   tlen = (const int*)  d_in[3];
    const float* W1   = (const float*)d_in[4];
    const float* b1   = (const float*)d_in[5];
    const float* W2   = (const float*)d_in[6];
    const float* b2   = (const float*)d_in[7];
    float* out = (float*)d_out;

    dim3 g1((TT + 127) / 128, DD / 128, BB);       // (8, 8, 32)
    gemm1_kernel<<<g1, 256>>>(dec, W1, b1);

    gemm2_kernel<<<(BB * TT) / 64, dim3(80, 4)>>>(W2, b2);

    logsoftmax_kernel<<<(BB * TT + 7) / 8, 256>>>();

    ctc_kernel<<<BB, 448>>>(tgt, dlen, tlen);

    reduce_kernel<<<1, 32>>>(out);
}

// round 5
// speedup vs baseline: 1.3038x; 1.3038x over previous
#include <cuda_runtime.h>
#include <cuda_bf16.h>
#include <math.h>
#include <stdint.h>

#define BB 32
#define DD 1024
#define TT 1000
#define TP 1024
#define VV 80
#define LMAX 200
#define BLANK 79
#define NEGV (-1e30f)

#if defined(__CUDA_ARCH_FEAT_SM103_ALL) || defined(__CUDA_ARCH_FEAT_SM100_ALL)
#define HAS_TCGEN05 1
#else
#define HAS_TCGEN05 0
#endif

// ---------------- scratch (static device globals; no allocation) -----------
__device__ __nv_bfloat16 g_xh[(size_t)BB * TP * DD];   // dec bf16 hi, [b][t][d]
__device__ __nv_bfloat16 g_xl[(size_t)BB * TP * DD];   // dec bf16 lo
__device__ __nv_bfloat16 g_w1h[(size_t)DD * DD];       // W1 hi, [e][d]
__device__ __nv_bfloat16 g_w1l[(size_t)DD * DD];       // W1 lo
__device__ float         g_h[(size_t)BB * TP * DD];    // fp32 h = relu(xW1+b1)
__device__ float         g_lp[(size_t)BB * TT * VV];   // log-probs (dense [b*TT+t])
__device__ float         g_loss[BB];

// ---------------- PTX helpers ----------------------------------------------
__device__ __forceinline__ uint32_t sm_u32(const void* p) {
    uint32_t a;
    asm("{ .reg .u64 t; cvta.to.shared.u64 t, %1; cvt.u32.u64 %0, t; }"
        : "=r"(a) : "l"(p));
    return a;
}
__device__ __forceinline__ bool elect1() {
    uint32_t p;
    asm volatile("{ .reg .pred p; elect.sync _|p, 0xFFFFFFFF; selp.b32 %0,1,0,p; }"
                 : "=r"(p));
    return p != 0;
}
__device__ __forceinline__ uint32_t swz(uint32_t off) {         // SW128
    return off ^ ((off >> 3) & 0x70u);
}
__device__ __forceinline__ uint64_t mkdesc(uint32_t addr) {     // K-major SW128
    const uint64_t base = (2ull << 61) | (1ull << 46) | (64ull << 32) | (1ull << 16);
    return base | (uint64_t)((addr >> 4) & 0x3FFF);
}
__device__ __forceinline__ void cp16(uint32_t dst, const void* src) {
    asm volatile("cp.async.cg.shared.global [%0], [%1], 16;" :: "r"(dst), "l"(src));
}
#define CP_COMMIT() asm volatile("cp.async.commit_group;" ::: "memory")
__device__ __forceinline__ void mbar_wait(uint32_t mbar, uint32_t parity) {
    asm volatile(
        "{\n\t.reg .pred P;\n\t"
        "WL%=:\n\t"
        "mbarrier.try_wait.parity.acquire.cta.shared::cta.b64 P, [%0], %1;\n\t"
        "@!P bra WL%=;\n\t}"
        :: "r"(mbar), "r"(parity) : "memory");
}

#if HAS_TCGEN05
__device__ __forceinline__ void mma_bf16_ss(uint32_t d, uint64_t ad, uint64_t bd,
                                            uint32_t idesc, bool acc) {
    uint32_t en = acc ? 1u : 0u;
    asm volatile(
        "{\n\t.reg .pred p;\n\t"
        "setp.ne.u32 p, %5, 0;\n\t"
        "tcgen05.mma.cta_group::1.kind::f16 [%0], %1, %2, %3, {%4,%4,%4,%4}, p;\n\t}"
        :: "r"(d), "l"(ad), "l"(bd), "r"(idesc), "r"(0u), "r"(en) : "memory");
}
#define LDTM_X32(r, a) asm volatile( \
    "tcgen05.ld.sync.aligned.32x32b.x32.b32 " \
    "{%0,%1,%2,%3,%4,%5,%6,%7,%8,%9,%10,%11,%12,%13,%14,%15," \
    "%16,%17,%18,%19,%20,%21,%22,%23,%24,%25,%26,%27,%28,%29,%30,%31}, [%32];" \
    : "=r"((r)[0]),"=r"((r)[1]),"=r"((r)[2]),"=r"((r)[3]), \
      "=r"((r)[4]),"=r"((r)[5]),"=r"((r)[6]),"=r"((r)[7]), \
      "=r"((r)[8]),"=r"((r)[9]),"=r"((r)[10]),"=r"((r)[11]), \
      "=r"((r)[12]),"=r"((r)[13]),"=r"((r)[14]),"=r"((r)[15]), \
      "=r"((r)[16]),"=r"((r)[17]),"=r"((r)[18]),"=r"((r)[19]), \
      "=r"((r)[20]),"=r"((r)[21]),"=r"((r)[22]),"=r"((r)[23]), \
      "=r"((r)[24]),"=r"((r)[25]),"=r"((r)[26]),"=r"((r)[27]), \
      "=r"((r)[28]),"=r"((r)[29]),"=r"((r)[30]),"=r"((r)[31]) \
    : "r"(a))
#define TM_WAIT_LD() asm volatile("tcgen05.wait::ld.sync.aligned;" ::: "memory")
#endif

// ---------------- pre-pass: split fp32 -> bf16 hi/lo ------------------------
__global__ __launch_bounds__(256) void k_prep_dec(const float* __restrict__ dec) {
    __shared__ float s[32][33];
    const int b = blockIdx.z, t0 = blockIdx.x * 32, d0 = blockIdx.y * 32;
    const int tx = threadIdx.x, ty = threadIdx.y;
    const float* in = dec + (size_t)b * DD * TT;
#pragma unroll
    for (int i = 0; i < 4; i++) {
        int d = d0 + ty + 8 * i, t = t0 + tx;
        s[ty + 8 * i][tx] = (t < TT) ? in[(size_t)d * TT + t] : 0.f;
    }
    __syncthreads();
#pragma unroll
    for (int i = 0; i < 4; i++) {
        int t = t0 + ty + 8 * i, d = d0 + tx;
        float v = s[tx][ty + 8 * i];
        __nv_bfloat16 hi = __float2bfloat16_rn(v);
        __nv_bfloat16 lo = __float2bfloat16_rn(v - __bfloat162float(hi));
        size_t idx = (size_t)b * TP * DD + (size_t)t * DD + d;
        g_xh[idx] = hi;
        g_xl[idx] = lo;
    }
}
__global__ __launch_bounds__(256) void k_prep_w1(const float* __restrict__ W1) {
    __shared__ float s[32][33];
    const int e0 = blockIdx.x * 32, d0 = blockIdx.y * 32;
    const int tx = threadIdx.x, ty = threadIdx.y;
#pragma unroll
    for (int i = 0; i < 4; i++)
        s[ty + 8 * i][tx] = W1[(size_t)(d0 + ty + 8 * i) * DD + e0 + tx];
    __syncthreads();
#pragma unroll
    for (int i = 0; i < 4; i++) {
        float v = s[tx][ty + 8 * i];
        __nv_bfloat16 hi = __float2bfloat16_rn(v);
        __nv_bfloat16 lo = __float2bfloat16_rn(v - __bfloat162float(hi));
        size_t idx = (size_t)(e0 + ty + 8 * i) * DD + d0 + tx;
        g_w1h[idx] = hi;
        g_w1l[idx] = lo;
    }
}

// ---------------- GEMM1: h = relu(x W1 + b1), split-bf16 tcgen05 ------------
// Stage layout (64KB): [Ah 16K][Al 16K][Bh 16K][Bl 16K], 128B rows, SW128.
__global__ __launch_bounds__(256) void k_gemm1(const float* __restrict__ dec,
                                               const float* __restrict__ W1,
                                               const float* __restrict__ b1) {
    const int tid = threadIdx.x;
    const int b = blockIdx.z, m0 = blockIdx.x * 128, n0 = blockIdx.y * 128;

#if HAS_TCGEN05
    constexpr int MSZ = 16384;          // one matrix tile
    constexpr int STAGE = 4 * MSZ;      // 64KB
    extern __shared__ char dyn_raw[];
    __shared__ uint32_t s_tmem;
    __shared__ __align__(8) uint64_t s_mbar;

    const int wid = tid >> 5, lid = tid & 31;
    const uint32_t raw = sm_u32(dyn_raw);
    const uint32_t sb = (raw + 1023u) & ~1023u;
    char* dynsm = dyn_raw + (sb - raw);

    if (wid == 0) {
        asm volatile("tcgen05.alloc.cta_group::1.sync.aligned.shared::cta.b32 [%0], %1;"
                     :: "r"(sm_u32(&s_tmem)), "r"(128u) : "memory");
        asm volatile("tcgen05.relinquish_alloc_permit.cta_group::1.sync.aligned;");
        if (elect1())
            asm volatile("mbarrier.init.shared.b64 [%0], 1;"
                         :: "r"(sm_u32(&s_mbar)) : "memory");
    }
    __syncthreads();
    const uint32_t tmem = s_tmem;
    const uint32_t mbar = sm_u32(&s_mbar);

    const __nv_bfloat16* Ah = g_xh + (size_t)b * TP * DD + (size_t)m0 * DD;
    const __nv_bfloat16* Al = g_xl + (size_t)b * TP * DD + (size_t)m0 * DD;
    const __nv_bfloat16* Bh = g_w1h + (size_t)n0 * DD;
    const __nv_bfloat16* Bl = g_w1l + (size_t)n0 * DD;

    // load one stage: 4096 x 16B chunks over 256 threads = 16 each
    auto ldstage = [&](int st, int kb) {
        const int k0 = kb * 64;
        const uint32_t su = sb + st * STAGE;
#pragma unroll
        for (int i = 0; i < 16; i++) {
            int c = tid + i * 256;           // 0..4095
            int mat = c >> 10;               // 0 Ah, 1 Al, 2 Bh, 3 Bl
            int cc = c & 1023;
            int r = cc >> 3, ch = cc & 7;
            const __nv_bfloat16* base = (mat == 0) ? Ah : (mat == 1) ? Al
                                      : (mat == 2) ? Bh : Bl;
            cp16(su + mat * MSZ + swz((uint32_t)(r * 128 + ch * 16)),
                 base + (size_t)r * DD + k0 + ch * 8);
        }
    };

    ldstage(0, 0);
    CP_COMMIT();

    const uint32_t idesc = (1u << 4) | (1u << 7) | (1u << 10) |
                           (16u << 17) | (8u << 24);   // F32 acc, bf16, N=128, M=128

    for (int kb = 0; kb < DD / 64; kb++) {
        const int st = kb & 1;
        if (kb + 1 < DD / 64) ldstage(st ^ 1, kb + 1);
        CP_COMMIT();
        asm volatile("cp.async.wait_group 1;" ::: "memory");
        __syncthreads();
        if (wid == 0) {
            asm volatile("fence.proxy.async.shared::cta;" ::: "memory");
            if (elect1()) {
                const uint32_t su = sb + st * STAGE;
                uint64_t ah = mkdesc(su);
                uint64_t al = mkdesc(su + MSZ);
                uint64_t bh = mkdesc(su + 2 * MSZ);
                uint64_t bl = mkdesc(su + 3 * MSZ);
#pragma unroll
                for (int s4 = 0; s4 < 4; s4++) {
                    mma_bf16_ss(tmem, ah + 2 * s4, bh + 2 * s4, idesc,
                                !(kb == 0 && s4 == 0));
                    mma_bf16_ss(tmem, ah + 2 * s4, bl + 2 * s4, idesc, true);
                    mma_bf16_ss(tmem, al + 2 * s4, bh + 2 * s4, idesc, true);
                }
                asm volatile(
                    "tcgen05.commit.cta_group::1.mbarrier::arrive::one.shared::cluster.b64 [%0];"
                    :: "r"(mbar) : "memory");
            }
        }
        mbar_wait(mbar, (uint32_t)(kb & 1));
    }

    asm volatile("tcgen05.fence::after_thread_sync;" ::: "memory");
    __syncthreads();

    // epilogue: TMEM -> smem (warps 0-3), then bias+relu -> g_h fp32 coalesced
    float* sh = (float*)dynsm;  // [128][129]
    if (wid < 4) {
        const int row = wid * 32 + lid;
#pragma unroll
        for (int c4 = 0; c4 < 4; c4++) {
            uint32_t r[32];
            LDTM_X32(r, tmem + c4 * 32);
            TM_WAIT_LD();
#pragma unroll
            for (int j = 0; j < 32; j++)
                sh[row * 129 + c4 * 32 + j] = __uint_as_float(r[j]);
        }
        asm volatile("tcgen05.fence::before_thread_sync;" ::: "memory");
    }
    __syncthreads();
#pragma unroll 4
    for (int i = 0; i < 64; i++) {
        int idx = tid + i * 256;
        int r = idx >> 7, c = idx & 127;
        float v = fmaxf(sh[r * 129 + c] + b1[n0 + c], 0.f);
        g_h[((size_t)b * TP + m0 + r) * DD + n0 + c] = v;
    }
    __syncthreads();
    if (wid == 0)
        asm volatile("tcgen05.dealloc.cta_group::1.sync.aligned.b32 %0, %1;"
                     :: "r"(tmem), "r"(128u));

#else  // ------------- SIMT fp32 fallback (R1 gemm1, correctness-verified) ---
    __shared__ float As[16][128];
    __shared__ float Bs[16][128];
    const int tx = tid & 15, ty = tid >> 4;
    const float* A = dec + (size_t)b * DD * TT;

    float acc[8][8];
#pragma unroll
    for (int i = 0; i < 8; i++)
#pragma unroll
        for (int j = 0; j < 8; j++) acc[i][j] = 0.f;

    for (int k0 = 0; k0 < DD; k0 += 16) {
#pragma unroll
        for (int i = 0; i < 8; i++) {
            int idx = tid + i * 256;
            int kk = idx >> 7, mm = idx & 127;
            int m = m0 + mm;
            As[kk][mm] = (m < TT) ? A[(size_t)(k0 + kk) * TT + m] : 0.f;
            Bs[kk][mm] = W1[(size_t)(k0 + kk) * DD + n0 + mm];
        }
        __syncthreads();
#pragma unroll
        for (int kk = 0; kk < 16; kk++) {
            float a[8], w[8];
#pragma unroll
            for (int i = 0; i < 8; i++) a[i] = As[kk][ty * 8 + i];
#pragma unroll
            for (int j = 0; j < 8; j++) w[j] = Bs[kk][tx * 8 + j];
#pragma unroll
            for (int i = 0; i < 8; i++)
#pragma unroll
                for (int j = 0; j < 8; j++) acc[i][j] = fmaf(a[i], w[j], acc[i][j]);
        }
        __syncthreads();
    }
#pragma unroll
    for (int i = 0; i < 8; i++) {
        int m = m0 + ty * 8 + i;
        float* hrow = g_h + ((size_t)b * TP + m) * DD;
#pragma unroll
        for (int j = 0; j < 8; j++) {
            int n = n0 + tx * 8 + j;
            hrow[n] = fmaxf(acc[i][j] + b1[n], 0.f);
        }
    }
#endif
}

// ---------------- GEMM2 (R1, fp32 SIMT): logits = h.W2 + b2 -----------------
__global__ __launch_bounds__(320) void gemm2_kernel(const float* __restrict__ W2,
                                                    const float* __restrict__ b2) {
    __shared__ float Hs[16][64];
    __shared__ float Ws[16][VV];

    const int b = blockIdx.y;
    const int t0 = blockIdx.x * 64;
    const size_t base = (size_t)b * TP + t0;
    const int v = threadIdx.x;   // 0..79
    const int ty = threadIdx.y;  // 0..3
    const int tid = ty * 80 + v;

    float acc[16];
#pragma unroll
    for (int r = 0; r < 16; r++) acc[r] = 0.f;

    for (int k0 = 0; k0 < DD; k0 += 16) {
        for (int idx = tid; idx < 64 * 16; idx += 320) {
            int kk = idx & 15, r = idx >> 4;
            Hs[kk][r] = g_h[(base + r) * DD + k0 + kk];
        }
        for (int idx = tid; idx < 16 * VV; idx += 320) {
            int vv = idx % VV, kk = idx / VV;
            Ws[kk][vv] = W2[(size_t)(k0 + kk) * VV + vv];
        }
        __syncthreads();
#pragma unroll
        for (int kk = 0; kk < 16; kk++) {
            float w = Ws[kk][v];
#pragma unroll
            for (int r = 0; r < 16; r++)
                acc[r] = fmaf(Hs[kk][ty + 4 * r], w, acc[r]);
        }
        __syncthreads();
    }

    float bias = b2[v];
#pragma unroll
    for (int r = 0; r < 16; r++) {
        int t = t0 + ty + 4 * r;
        if (t < TT)
            g_lp[((size_t)b * TT + t) * VV + v] = acc[r] + bias;
    }
}

// ---------------- log_softmax in place (R1) ---------------------------------
__global__ __launch_bounds__(256) void logsoftmax_kernel() {
    const int row = blockIdx.x * 8 + (threadIdx.x >> 5);
    const int lane = threadIdx.x & 31;
    if (row >= BB * TT) return;
    float* p = g_lp + (size_t)row * VV;

    float mx = -INFINITY;
    for (int j = lane; j < VV; j += 32) mx = fmaxf(mx, p[j]);
#pragma unroll
    for (int o = 16; o > 0; o >>= 1) mx = fmaxf(mx, __shfl_xor_sync(0xffffffffu, mx, o));

    float s = 0.f;
    for (int j = lane; j < VV; j += 32) s += expf(p[j] - mx);
#pragma unroll
    for (int o = 16; o > 0; o >>= 1) s += __shfl_xor_sync(0xffffffffu, s, o);

    float lse = mx + logf(s);
    for (int j = lane; j < VV; j += 32) p[j] -= lse;
}

// ---------------- CTC DP (R1, direct loads) ---------------------------------
__global__ __launch_bounds__(448) void ctc_kernel(const int* __restrict__ tgt,
                                                  const int* __restrict__ dlen,
                                                  const int* __restrict__ tlen) {
    const int b = blockIdx.x;
    const int L = tlen[b];
    const int S = 2 * L + 1;
    const int len = dlen[b];
    const int s = threadIdx.x;

    __shared__ float A[2][2 * LMAX + 1];
    __shared__ int ext[2 * LMAX + 1];
    __shared__ unsigned char skip[2 * LMAX + 1];

    const float* lpb = g_lp + (size_t)b * TT * VV;

    if (s < S) ext[s] = (s & 1) ? tgt[b * LMAX + (s >> 1)] : BLANK;
    __syncthreads();
    if (s < S) {
        skip[s] = ((s & 1) && s >= 3 && ext[s] != ext[s - 2]) ? 1 : 0;
        float a0 = NEGV;
        if (s == 0)      a0 = lpb[BLANK];
        else if (s == 1) a0 = lpb[ext[1]];
        A[0][s] = a0;
    }
    __syncthreads();

    for (int t = 1; t < len; t++) {
        const int cur = t & 1, prev = cur ^ 1;
        if (s < S) {
            float a = A[prev][s];
            float bv = (s >= 1) ? A[prev][s - 1] : NEGV;
            float cv = skip[s] ? A[prev][s - 2] : NEGV;
            float m = fmaxf(a, fmaxf(bv, cv));
            float v = m + logf(expf(a - m) + expf(bv - m) + expf(cv - m));
            A[cur][s] = v + lpb[t * VV + ext[s]];
        }
        __syncthreads();
    }

    if (s == 0) {
        const int f = (len - 1) & 1;
        float l1 = A[f][2 * L - 1];
        float l2 = A[f][2 * L];
        float m = fmaxf(l1, l2);
        float last = m + logf(expf(l1 - m) + expf(l2 - m));
        float nll = (last > 0.5f * NEGV) ? -last : 0.f;
        g_loss[b] = nll / (float)len;
    }
}

__global__ __launch_bounds__(32) void k_reduce(float* __restrict__ out) {
    float v = g_loss[threadIdx.x];
#pragma unroll
    for (int o = 16; o > 0; o >>= 1) v += __shfl_xor_sync(0xffffffffu, v, o);
    if (threadIdx.x == 0) out[0] = v * (1.0f / BB);
}

// ---------------------------------------------------------------------------
extern "C" void kernel_launch(void* const* d_in, const int* in_sizes, int n_in,
                              void* d_out, int out_size) {
    const float* dec  = (const float*)d_in[0];
    const int*   tgt  = (const int*)d_in[1];
    const int*   dlen = (const int*)d_in[2];
    const int*   tlen = (const int*)d_in[3];
    const float* W1   = (const float*)d_in[4];
    const float* b1   = (const float*)d_in[5];
    const float* W2   = (const float*)d_in[6];
    const float* b2   = (const float*)d_in[7];
    float* out = (float*)d_out;

    const int SMEM1 = 132096;  // 1KB align pad + 2 x 64KB stages (epi reuses)
    cudaFuncSetAttribute(k_gemm1, cudaFuncAttributeMaxDynamicSharedMemorySize, SMEM1);

    k_prep_dec<<<dim3(TP / 32, DD / 32, BB), dim3(32, 8)>>>(dec);
    k_prep_w1<<<dim3(DD / 32, DD / 32), dim3(32, 8)>>>(W1);

    k_gemm1<<<dim3(TP / 128, DD / 128, BB), 256, SMEM1>>>(dec, W1, b1);

    gemm2_kernel<<<dim3(TP / 64, BB), dim3(80, 4)>>>(W2, b2);
    logsoftmax_kernel<<<(BB * TT + 7) / 8, 256>>>();
    ctc_kernel<<<BB, 448>>>(tgt, dlen, tlen);
    k_reduce<<<1, 32>>>(out);
}

// round 6
// speedup vs baseline: 3.9974x; 3.0659x over previous
#include <cuda_runtime.h>
#include <cuda_bf16.h>
#include <math.h>
#include <stdint.h>

#define BB 32
#define DD 1024
#define TT 1000
#define TP 1024
#define VV 80
#define NTB 96
#define LMAX 200
#define BLANK 79
#define NEGV (-1e30f)

#if defined(__CUDA_ARCH_FEAT_SM103_ALL) || defined(__CUDA_ARCH_FEAT_SM100_ALL)
#define HAS_TCGEN05 1
#else
#define HAS_TCGEN05 0
#endif

// ---------------- scratch ----------------------------------------------------
__device__ __nv_bfloat16 g_xh[(size_t)BB * TP * DD];   // dec hi, [b][t][d]
__device__ __nv_bfloat16 g_xl[(size_t)BB * TP * DD];   // dec lo
__device__ __nv_bfloat16 g_w1h[(size_t)DD * DD];       // W1 hi, [e][d]
__device__ __nv_bfloat16 g_w1l[(size_t)DD * DD];       // W1 lo
__device__ __nv_bfloat16 g_w2h[(size_t)NTB * DD];      // W2 hi, [v][d], v>=VV zero
__device__ __nv_bfloat16 g_w2l[(size_t)NTB * DD];      // W2 lo
__device__ __nv_bfloat16 g_hh[(size_t)BB * TP * DD];   // h hi, [b][t][d]
__device__ __nv_bfloat16 g_hl[(size_t)BB * TP * DD];   // h lo
__device__ float         g_lp[(size_t)BB * TT * VV];   // log-probs
__device__ float         g_loss[BB];

// ---------------- PTX helpers ------------------------------------------------
__device__ __forceinline__ uint32_t sm_u32(const void* p) {
    uint32_t a;
    asm("{ .reg .u64 t; cvta.to.shared.u64 t, %1; cvt.u32.u64 %0, t; }"
        : "=r"(a) : "l"(p));
    return a;
}
__device__ __forceinline__ bool elect1() {
    uint32_t p;
    asm volatile("{ .reg .pred p; elect.sync _|p, 0xFFFFFFFF; selp.b32 %0,1,0,p; }"
                 : "=r"(p));
    return p != 0;
}
__device__ __forceinline__ uint32_t swz(uint32_t off) { return off ^ ((off >> 3) & 0x70u); }
__device__ __forceinline__ uint64_t mkdesc(uint32_t addr) {
    const uint64_t base = (2ull << 61) | (1ull << 46) | (64ull << 32) | (1ull << 16);
    return base | (uint64_t)((addr >> 4) & 0x3FFF);
}
__device__ __forceinline__ void cp16(uint32_t dst, const void* src) {
    asm volatile("cp.async.cg.shared.global [%0], [%1], 16;" :: "r"(dst), "l"(src));
}
#define CP_COMMIT() asm volatile("cp.async.commit_group;" ::: "memory")
__device__ __forceinline__ void mbar_wait(uint32_t mbar, uint32_t parity) {
    asm volatile(
        "{\n\t.reg .pred P;\n\t"
        "WL%=:\n\t"
        "mbarrier.try_wait.parity.acquire.cta.shared::cta.b64 P, [%0], %1;\n\t"
        "@!P bra WL%=;\n\t}"
        :: "r"(mbar), "r"(parity) : "memory");
}

#if HAS_TCGEN05
__device__ __forceinline__ void mma_bf16_ss(uint32_t d, uint64_t ad, uint64_t bd,
                                            uint32_t idesc, bool acc) {
    uint32_t en = acc ? 1u : 0u;
    asm volatile(
        "{\n\t.reg .pred p;\n\t"
        "setp.ne.u32 p, %5, 0;\n\t"
        "tcgen05.mma.cta_group::1.kind::f16 [%0], %1, %2, %3, {%4,%4,%4,%4}, p;\n\t}"
        :: "r"(d), "l"(ad), "l"(bd), "r"(idesc), "r"(0u), "r"(en) : "memory");
}
#define LDTM_X32(r, a) asm volatile( \
    "tcgen05.ld.sync.aligned.32x32b.x32.b32 " \
    "{%0,%1,%2,%3,%4,%5,%6,%7,%8,%9,%10,%11,%12,%13,%14,%15," \
    "%16,%17,%18,%19,%20,%21,%22,%23,%24,%25,%26,%27,%28,%29,%30,%31}, [%32];" \
    : "=r"((r)[0]),"=r"((r)[1]),"=r"((r)[2]),"=r"((r)[3]), \
      "=r"((r)[4]),"=r"((r)[5]),"=r"((r)[6]),"=r"((r)[7]), \
      "=r"((r)[8]),"=r"((r)[9]),"=r"((r)[10]),"=r"((r)[11]), \
      "=r"((r)[12]),"=r"((r)[13]),"=r"((r)[14]),"=r"((r)[15]), \
      "=r"((r)[16]),"=r"((r)[17]),"=r"((r)[18]),"=r"((r)[19]), \
      "=r"((r)[20]),"=r"((r)[21]),"=r"((r)[22]),"=r"((r)[23]), \
      "=r"((r)[24]),"=r"((r)[25]),"=r"((r)[26]),"=r"((r)[27]), \
      "=r"((r)[28]),"=r"((r)[29]),"=r"((r)[30]),"=r"((r)[31]) \
    : "r"(a))
#define LDTM_X16(r, a) asm volatile( \
    "tcgen05.ld.sync.aligned.32x32b.x16.b32 " \
    "{%0,%1,%2,%3,%4,%5,%6,%7,%8,%9,%10,%11,%12,%13,%14,%15}, [%16];" \
    : "=r"((r)[0]),"=r"((r)[1]),"=r"((r)[2]),"=r"((r)[3]), \
      "=r"((r)[4]),"=r"((r)[5]),"=r"((r)[6]),"=r"((r)[7]), \
      "=r"((r)[8]),"=r"((r)[9]),"=r"((r)[10]),"=r"((r)[11]), \
      "=r"((r)[12]),"=r"((r)[13]),"=r"((r)[14]),"=r"((r)[15]) \
    : "r"(a))
#define TM_WAIT_LD() asm volatile("tcgen05.wait::ld.sync.aligned;" ::: "memory")
#endif

// ---------------- pre-passes -------------------------------------------------
__global__ __launch_bounds__(256) void k_prep_dec(const float* __restrict__ dec) {
    __shared__ float s[32][33];
    const int b = blockIdx.z, t0 = blockIdx.x * 32, d0 = blockIdx.y * 32;
    const int tx = threadIdx.x, ty = threadIdx.y;
    const float* in = dec + (size_t)b * DD * TT;
#pragma unroll
    for (int i = 0; i < 4; i++) {
        int d = d0 + ty + 8 * i, t = t0 + tx;
        s[ty + 8 * i][tx] = (t < TT) ? in[(size_t)d * TT + t] : 0.f;
    }
    __syncthreads();
#pragma unroll
    for (int i = 0; i < 4; i++) {
        int t = t0 + ty + 8 * i, d = d0 + tx;
        float v = s[tx][ty + 8 * i];
        __nv_bfloat16 hi = __float2bfloat16_rn(v);
        __nv_bfloat16 lo = __float2bfloat16_rn(v - __bfloat162float(hi));
        size_t idx = (size_t)b * TP * DD + (size_t)t * DD + d;
        g_xh[idx] = hi;
        g_xl[idx] = lo;
    }
}
__global__ __launch_bounds__(256) void k_prep_w1(const float* __restrict__ W1) {
    __shared__ float s[32][33];
    const int e0 = blockIdx.x * 32, d0 = blockIdx.y * 32;
    const int tx = threadIdx.x, ty = threadIdx.y;
#pragma unroll
    for (int i = 0; i < 4; i++)
        s[ty + 8 * i][tx] = W1[(size_t)(d0 + ty + 8 * i) * DD + e0 + tx];
    __syncthreads();
#pragma unroll
    for (int i = 0; i < 4; i++) {
        float v = s[tx][ty + 8 * i];
        __nv_bfloat16 hi = __float2bfloat16_rn(v);
        __nv_bfloat16 lo = __float2bfloat16_rn(v - __bfloat162float(hi));
        size_t idx = (size_t)(e0 + ty + 8 * i) * DD + d0 + tx;
        g_w1h[idx] = hi;
        g_w1l[idx] = lo;
    }
}
__global__ __launch_bounds__(256) void k_prep_w2(const float* __restrict__ W2) {
    int idx = blockIdx.x * 256 + threadIdx.x;
    if (idx < NTB * DD) {
        int v = idx / DD, d = idx - v * DD;
        float x = (v < VV) ? W2[(size_t)d * VV + v] : 0.f;
        __nv_bfloat16 hi = __float2bfloat16_rn(x);
        __nv_bfloat16 lo = __float2bfloat16_rn(x - __bfloat162float(hi));
        g_w2h[idx] = hi;
        g_w2l[idx] = lo;
    }
}

// ---------------- GEMM1: h(hi/lo) = relu(x W1 + b1), split-bf16 tcgen05 ------
__global__ __launch_bounds__(256) void k_gemm1(const float* __restrict__ dec,
                                               const float* __restrict__ W1,
                                               const float* __restrict__ b1) {
    const int tid = threadIdx.x;
    const int b = blockIdx.z, m0 = blockIdx.x * 128, n0 = blockIdx.y * 128;

#if HAS_TCGEN05
    constexpr int MSZ = 16384;
    constexpr int STAGE = 4 * MSZ;   // [Ah][Al][Bh][Bl] 64KB
    extern __shared__ char dyn_raw[];
    __shared__ uint32_t s_tmem;
    __shared__ __align__(8) uint64_t s_mbar;

    const int wid = tid >> 5, lid = tid & 31;
    const uint32_t raw = sm_u32(dyn_raw);
    const uint32_t sb = (raw + 1023u) & ~1023u;
    char* dynsm = dyn_raw + (sb - raw);

    if (wid == 0) {
        asm volatile("tcgen05.alloc.cta_group::1.sync.aligned.shared::cta.b32 [%0], %1;"
                     :: "r"(sm_u32(&s_tmem)), "r"(128u) : "memory");
        asm volatile("tcgen05.relinquish_alloc_permit.cta_group::1.sync.aligned;");
        if (elect1())
            asm volatile("mbarrier.init.shared.b64 [%0], 1;"
                         :: "r"(sm_u32(&s_mbar)) : "memory");
    }
    __syncthreads();
    const uint32_t tmem = s_tmem;
    const uint32_t mbar = sm_u32(&s_mbar);

    const __nv_bfloat16* Ah = g_xh + (size_t)b * TP * DD + (size_t)m0 * DD;
    const __nv_bfloat16* Al = g_xl + (size_t)b * TP * DD + (size_t)m0 * DD;
    const __nv_bfloat16* Bh = g_w1h + (size_t)n0 * DD;
    const __nv_bfloat16* Bl = g_w1l + (size_t)n0 * DD;

    auto ldstage = [&](int st, int kb) {
        const int k0 = kb * 64;
        const uint32_t su = sb + st * STAGE;
#pragma unroll
        for (int i = 0; i < 16; i++) {
            int c = tid + i * 256;
            int mat = c >> 10;
            int cc = c & 1023;
            int r = cc >> 3, ch = cc & 7;
            const __nv_bfloat16* base = (mat == 0) ? Ah : (mat == 1) ? Al
                                      : (mat == 2) ? Bh : Bl;
            cp16(su + mat * MSZ + swz((uint32_t)(r * 128 + ch * 16)),
                 base + (size_t)r * DD + k0 + ch * 8);
        }
    };

    ldstage(0, 0);
    CP_COMMIT();

    const uint32_t idesc = (1u << 4) | (1u << 7) | (1u << 10) |
                           (16u << 17) | (8u << 24);

    for (int kb = 0; kb < DD / 64; kb++) {
        const int st = kb & 1;
        if (kb + 1 < DD / 64) ldstage(st ^ 1, kb + 1);
        CP_COMMIT();
        asm volatile("cp.async.wait_group 1;" ::: "memory");
        __syncthreads();
        if (wid == 0) {
            asm volatile("fence.proxy.async.shared::cta;" ::: "memory");
            if (elect1()) {
                const uint32_t su = sb + st * STAGE;
                uint64_t ah = mkdesc(su);
                uint64_t al = mkdesc(su + MSZ);
                uint64_t bh = mkdesc(su + 2 * MSZ);
                uint64_t bl = mkdesc(su + 3 * MSZ);
#pragma unroll
                for (int s4 = 0; s4 < 4; s4++) {
                    mma_bf16_ss(tmem, ah + 2 * s4, bh + 2 * s4, idesc,
                                !(kb == 0 && s4 == 0));
                    mma_bf16_ss(tmem, ah + 2 * s4, bl + 2 * s4, idesc, true);
                    mma_bf16_ss(tmem, al + 2 * s4, bh + 2 * s4, idesc, true);
                }
                asm volatile(
                    "tcgen05.commit.cta_group::1.mbarrier::arrive::one.shared::cluster.b64 [%0];"
                    :: "r"(mbar) : "memory");
            }
        }
        mbar_wait(mbar, (uint32_t)(kb & 1));
    }

    asm volatile("tcgen05.fence::after_thread_sync;" ::: "memory");
    __syncthreads();

    // epilogue: TMEM -> smem fp32, then bias+relu -> split bf16 hi/lo
    float* sh = (float*)dynsm;  // [128][129]
    if (wid < 4) {
        const int row = wid * 32 + lid;
#pragma unroll
        for (int c4 = 0; c4 < 4; c4++) {
            uint32_t r[32];
            LDTM_X32(r, tmem + c4 * 32);
            TM_WAIT_LD();
#pragma unroll
            for (int j = 0; j < 32; j++)
                sh[row * 129 + c4 * 32 + j] = __uint_as_float(r[j]);
        }
        asm volatile("tcgen05.fence::before_thread_sync;" ::: "memory");
    }
    __syncthreads();
#pragma unroll 4
    for (int i = 0; i < 32; i++) {
        int idx = tid + i * 256;              // pair index over 128x64
        int r = idx >> 6, cp = (idx & 63) * 2;
        float v0 = fmaxf(sh[r * 129 + cp] + b1[n0 + cp], 0.f);
        float v1 = fmaxf(sh[r * 129 + cp + 1] + b1[n0 + cp + 1], 0.f);
        __nv_bfloat16 h0 = __float2bfloat16_rn(v0);
        __nv_bfloat16 h1 = __float2bfloat16_rn(v1);
        __nv_bfloat16 l0 = __float2bfloat16_rn(v0 - __bfloat162float(h0));
        __nv_bfloat16 l1 = __float2bfloat16_rn(v1 - __bfloat162float(h1));
        size_t off = ((size_t)b * TP + m0 + r) * DD + n0 + cp;
        *reinterpret_cast<__nv_bfloat162*>(&g_hh[off]) = __nv_bfloat162(h0, h1);
        *reinterpret_cast<__nv_bfloat162*>(&g_hl[off]) = __nv_bfloat162(l0, l1);
    }
    __syncthreads();
    if (wid == 0)
        asm volatile("tcgen05.dealloc.cta_group::1.sync.aligned.b32 %0, %1;"
                     :: "r"(tmem), "r"(128u));

#else  // SIMT fp32 fallback (compile-only on non-103a pass)
    __shared__ float As[16][128];
    __shared__ float Bs[16][128];
    const int tx = tid & 15, ty = tid >> 4;
    const float* A = dec + (size_t)b * DD * TT;
    float acc[8][8];
#pragma unroll
    for (int i = 0; i < 8; i++)
#pragma unroll
        for (int j = 0; j < 8; j++) acc[i][j] = 0.f;
    for (int k0 = 0; k0 < DD; k0 += 16) {
#pragma unroll
        for (int i = 0; i < 8; i++) {
            int idx = tid + i * 256;
            int kk = idx >> 7, mm = idx & 127;
            int m = m0 + mm;
            As[kk][mm] = (m < TT) ? A[(size_t)(k0 + kk) * TT + m] : 0.f;
            Bs[kk][mm] = W1[(size_t)(k0 + kk) * DD + n0 + mm];
        }
        __syncthreads();
#pragma unroll
        for (int kk = 0; kk < 16; kk++) {
            float a[8], w[8];
#pragma unroll
            for (int i = 0; i < 8; i++) a[i] = As[kk][ty * 8 + i];
#pragma unroll
            for (int j = 0; j < 8; j++) w[j] = Bs[kk][tx * 8 + j];
#pragma unroll
            for (int i = 0; i < 8; i++)
#pragma unroll
                for (int j = 0; j < 8; j++) acc[i][j] = fmaf(a[i], w[j], acc[i][j]);
        }
        __syncthreads();
    }
#pragma unroll
    for (int i = 0; i < 8; i++) {
        int m = m0 + ty * 8 + i;
#pragma unroll
        for (int j = 0; j < 8; j++) {
            int n = n0 + tx * 8 + j;
            float v = fmaxf(acc[i][j] + b1[n], 0.f);
            __nv_bfloat16 hi = __float2bfloat16_rn(v);
            size_t off = ((size_t)b * TP + m) * DD + n;
            g_hh[off] = hi;
            g_hl[off] = __float2bfloat16_rn(v - __bfloat162float(hi));
        }
    }
#endif
}

// ---------------- GEMM2 + fused bias/log-softmax, split-bf16 tcgen05 ---------
__global__ __launch_bounds__(256) void k_gemm2(const float* __restrict__ b2) {
    const int tid = threadIdx.x;
    const int b = blockIdx.y, m0 = blockIdx.x * 128;

#if HAS_TCGEN05
    constexpr int ASZ = 16384;
    constexpr int BSZ = NTB * 128;          // 12288
    constexpr int STAGE = 2 * ASZ + 2 * BSZ;  // 57344
    extern __shared__ char dyn_raw[];
    __shared__ uint32_t s_tmem;
    __shared__ __align__(8) uint64_t s_mbar;

    const int wid = tid >> 5, lid = tid & 31;
    const uint32_t raw = sm_u32(dyn_raw);
    const uint32_t sb = (raw + 1023u) & ~1023u;
    char* dynsm = dyn_raw + (sb - raw);

    if (wid == 0) {
        asm volatile("tcgen05.alloc.cta_group::1.sync.aligned.shared::cta.b32 [%0], %1;"
                     :: "r"(sm_u32(&s_tmem)), "r"(128u) : "memory");
        asm volatile("tcgen05.relinquish_alloc_permit.cta_group::1.sync.aligned;");
        if (elect1())
            asm volatile("mbarrier.init.shared.b64 [%0], 1;"
                         :: "r"(sm_u32(&s_mbar)) : "memory");
    }
    __syncthreads();
    const uint32_t tmem = s_tmem;
    const uint32_t mbar = sm_u32(&s_mbar);

    const __nv_bfloat16* Ah = g_hh + (size_t)b * TP * DD + (size_t)m0 * DD;
    const __nv_bfloat16* Al = g_hl + (size_t)b * TP * DD + (size_t)m0 * DD;

    auto ldstage = [&](int st, int kb) {
        const int k0 = kb * 64;
        const uint32_t su = sb + st * STAGE;
#pragma unroll
        for (int i = 0; i < 14; i++) {
            int c = tid + i * 256;  // 0..3583
            uint32_t dst;
            const __nv_bfloat16* src;
            if (c < 1024) {
                int r = c >> 3, ch = c & 7;
                dst = su + swz((uint32_t)(r * 128 + ch * 16));
                src = Ah + (size_t)r * DD + k0 + ch * 8;
            } else if (c < 2048) {
                int cc = c - 1024, r = cc >> 3, ch = cc & 7;
                dst = su + ASZ + swz((uint32_t)(r * 128 + ch * 16));
                src = Al + (size_t)r * DD + k0 + ch * 8;
            } else if (c < 2816) {
                int cc = c - 2048, r = cc >> 3, ch = cc & 7;
                dst = su + 2 * ASZ + swz((uint32_t)(r * 128 + ch * 16));
                src = g_w2h + (size_t)r * DD + k0 + ch * 8;
            } else {
                int cc = c - 2816, r = cc >> 3, ch = cc & 7;
                dst = su + 2 * ASZ + BSZ + swz((uint32_t)(r * 128 + ch * 16));
                src = g_w2l + (size_t)r * DD + k0 + ch * 8;
            }
            cp16(dst, src);
        }
    };

    ldstage(0, 0);
    CP_COMMIT();

    const uint32_t idesc = (1u << 4) | (1u << 7) | (1u << 10) |
                           ((uint32_t)(NTB / 8) << 17) | (8u << 24);

    for (int kb = 0; kb < DD / 64; kb++) {
        const int st = kb & 1;
        if (kb + 1 < DD / 64) ldstage(st ^ 1, kb + 1);
        CP_COMMIT();
        asm volatile("cp.async.wait_group 1;" ::: "memory");
        __syncthreads();
        if (wid == 0) {
            asm volatile("fence.proxy.async.shared::cta;" ::: "memory");
            if (elect1()) {
                const uint32_t su = sb + st * STAGE;
                uint64_t ah = mkdesc(su);
                uint64_t al = mkdesc(su + ASZ);
                uint64_t bh = mkdesc(su + 2 * ASZ);
                uint64_t bl = mkdesc(su + 2 * ASZ + BSZ);
#pragma unroll
                for (int s4 = 0; s4 < 4; s4++) {
                    mma_bf16_ss(tmem, ah + 2 * s4, bh + 2 * s4, idesc,
                                !(kb == 0 && s4 == 0));
                    mma_bf16_ss(tmem, ah + 2 * s4, bl + 2 * s4, idesc, true);
                    mma_bf16_ss(tmem, al + 2 * s4, bh + 2 * s4, idesc, true);
                }
                asm volatile(
                    "tcgen05.commit.cta_group::1.mbarrier::arrive::one.shared::cluster.b64 [%0];"
                    :: "r"(mbar) : "memory");
            }
        }
        mbar_wait(mbar, (uint32_t)(kb & 1));
    }

    asm volatile("tcgen05.fence::after_thread_sync;" ::: "memory");
    __syncthreads();

    // fused epilogue: bias + log-softmax per row (rows live one-per-lane, warps 0-3)
    float* sh = (float*)dynsm;  // [128][81]
    if (wid < 4) {
        float v[VV];
        {
            uint32_t r[32];
            LDTM_X32(r, tmem);
            TM_WAIT_LD();
#pragma unroll
            for (int j = 0; j < 32; j++) v[j] = __uint_as_float(r[j]);
        }
        {
            uint32_t r[32];
            LDTM_X32(r, tmem + 32);
            TM_WAIT_LD();
#pragma unroll
            for (int j = 0; j < 32; j++) v[32 + j] = __uint_as_float(r[j]);
        }
        {
            uint32_t r[16];
            LDTM_X16(r, tmem + 64);
            TM_WAIT_LD();
#pragma unroll
            for (int j = 0; j < 16; j++) v[64 + j] = __uint_as_float(r[j]);
        }
        asm volatile("tcgen05.fence::before_thread_sync;" ::: "memory");
        float mx = -1e30f;
#pragma unroll
        for (int j = 0; j < VV; j++) { v[j] += b2[j]; mx = fmaxf(mx, v[j]); }
        float sum = 0.f;
#pragma unroll
        for (int j = 0; j < VV; j++) sum += expf(v[j] - mx);
        const float lse = mx + logf(sum);
        const int row = wid * 32 + lid;
#pragma unroll
        for (int j = 0; j < VV; j++) sh[row * 81 + j] = v[j] - lse;
    }
    __syncthreads();
#pragma unroll 4
    for (int i = 0; i < 40; i++) {
        int idx = tid + i * 256;               // 0..10239
        int rr = idx / 80, cc = idx - rr * 80;
        int t = m0 + rr;
        if (t < TT) g_lp[((size_t)b * TT + t) * VV + cc] = sh[rr * 81 + cc];
    }
    __syncthreads();
    if (wid == 0)
        asm volatile("tcgen05.dealloc.cta_group::1.sync.aligned.b32 %0, %1;"
                     :: "r"(tmem), "r"(128u));

#else  // SIMT fallback (compile-only)
    const int r = m0 + tid % 128;
    if (tid < 128) {
        float v[VV];
        for (int j = 0; j < VV; j++) v[j] = b2[j];
        const __nv_bfloat16* hh = g_hh + ((size_t)b * TP + r) * DD;
        const __nv_bfloat16* hl = g_hl + ((size_t)b * TP + r) * DD;
        for (int k = 0; k < DD; k++) {
            float hv = __bfloat162float(hh[k]) + __bfloat162float(hl[k]);
            for (int j = 0; j < VV; j++)
                v[j] = fmaf(hv, __bfloat162float(g_w2h[(size_t)j * DD + k]) +
                                 __bfloat162float(g_w2l[(size_t)j * DD + k]), v[j]);
        }
        float mx = -1e30f;
        for (int j = 0; j < VV; j++) mx = fmaxf(mx, v[j]);
        float sum = 0.f;
        for (int j = 0; j < VV; j++) sum += expf(v[j] - mx);
        float lse = mx + logf(sum);
        if (r < TT + m0 - m0 && (m0 + tid % 128) < TP) {
            int t = r;
            if (t < TT)
                for (int j = 0; j < VV; j++)
                    g_lp[((size_t)b * TT + t) * VV + j] = v[j] - lse;
        }
    }
#endif
}

// ---------------- CTC DP: register prefetch + MUFU ---------------------------
__global__ __launch_bounds__(448) void k_ctc(const int* __restrict__ tgt,
                                             const int* __restrict__ dlen,
                                             const int* __restrict__ tlen) {
    const int b = blockIdx.x;
    const int L = tlen[b];
    const int S = 2 * L + 1;
    const int len = dlen[b];
    const int s = threadIdx.x;

    __shared__ float A[2][2 * LMAX + 1];
    __shared__ int ext[2 * LMAX + 1];
    __shared__ unsigned char skip[2 * LMAX + 1];

    const float* lpb = g_lp + (size_t)b * TT * VV;

    int lbl = BLANK;
    if (s < S) {
        lbl = (s & 1) ? tgt[b * LMAX + (s >> 1)] : BLANK;
        ext[s] = lbl;
    }
    __syncthreads();
    bool sk = false;
    if (s < S) {
        sk = ((s & 1) && s >= 3 && lbl != ext[s - 2]);
        skip[s] = sk;
        float a0 = NEGV;
        if (s == 0)      a0 = lpb[BLANK];
        else if (s == 1) a0 = lpb[lbl];
        A[0][s] = a0;
    }

    // 2-deep register prefetch of this state's emission log-prob
    float eA = 0.f, eB = 0.f;
    if (s < S) {
        int t1 = (1 < len) ? 1 : len - 1;
        int t2 = (2 < len) ? 2 : len - 1;
        eA = lpb[(size_t)t1 * VV + lbl];
        eB = lpb[(size_t)t2 * VV + lbl];
    }
    __syncthreads();

    for (int t = 1; t < len; t++) {
        const int cur = t & 1, prev = cur ^ 1;
        float e_cur = eA;
        eA = eB;
        if (s < S) {
            int tn = (t + 2 < len) ? t + 2 : len - 1;
            eB = lpb[(size_t)tn * VV + lbl];
            float a = A[prev][s];
            float bv = (s >= 1) ? A[prev][s - 1] : NEGV;
            float cv = sk ? A[prev][s - 2] : NEGV;
            float m = fmaxf(a, fmaxf(bv, cv));
            float v = m + __logf(__expf(a - m) + __expf(bv - m) + __expf(cv - m));
            A[cur][s] = v + e_cur;
        }
        __syncthreads();
    }

    if (s == 0) {
        const int f = (len - 1) & 1;
        float l1 = A[f][2 * L - 1];
        float l2 = A[f][2 * L];
        float m = fmaxf(l1, l2);
        float last = m + logf(expf(l1 - m) + expf(l2 - m));
        float nll = (last > 0.5f * NEGV) ? -last : 0.f;
        g_loss[b] = nll / (float)len;
    }
}

__global__ __launch_bounds__(32) void k_reduce(float* __restrict__ out) {
    float v = g_loss[threadIdx.x];
#pragma unroll
    for (int o = 16; o > 0; o >>= 1) v += __shfl_xor_sync(0xffffffffu, v, o);
    if (threadIdx.x == 0) out[0] = v * (1.0f / BB);
}

// ---------------------------------------------------------------------------
extern "C" void kernel_launch(void* const* d_in, const int* in_sizes, int n_in,
                              void* d_out, int out_size) {
    const float* dec  = (const float*)d_in[0];
    const int*   tgt  = (const int*)d_in[1];
    const int*   dlen = (const int*)d_in[2];
    const int*   tlen = (const int*)d_in[3];
    const float* W1   = (const float*)d_in[4];
    const float* b1   = (const float*)d_in[5];
    const float* W2   = (const float*)d_in[6];
    const float* b2   = (const float*)d_in[7];
    float* out = (float*)d_out;

    const int SMEM1 = 132096;  // pad + 2x64KB stages (epilogue reuses)
    const int SMEM2 = 115712;  // pad + 2x57344 stages (epilogue reuses)
    cudaFuncSetAttribute(k_gemm1, cudaFuncAttributeMaxDynamicSharedMemorySize, SMEM1);
    cudaFuncSetAttribute(k_gemm2, cudaFuncAttributeMaxDynamicSharedMemorySize, SMEM2);

    k_prep_dec<<<dim3(TP / 32, DD / 32, BB), dim3(32, 8)>>>(dec);
    k_prep_w1<<<dim3(DD / 32, DD / 32), dim3(32, 8)>>>(W1);
    k_prep_w2<<<(NTB * DD + 255) / 256, 256>>>(W2);

    k_gemm1<<<dim3(TP / 128, DD / 128, BB), 256, SMEM1>>>(dec, W1, b1);
    k_gemm2<<<dim3(TP / 128, BB), 256, SMEM2>>>(b2);

    k_ctc<<<BB, 448>>>(tgt, dlen, tlen);
    k_reduce<<<1, 32>>>(out);
}